// round 1
// baseline (speedup 1.0000x reference)
#include <cuda_runtime.h>
#include <cuda_bf16.h>
#include <math.h>

// ---------------------------------------------------------------------------
// GraphSAGE: mean-SAGE -> max-SAGE -> lstm-SAGE -> JumpingKnowledge bi-LSTM
// N=50000 nodes, K=16 fixed in-degree (dst = repeat(arange(N),16)), C=128.
// Round 0 baseline: fp32 smem-tiled dual GEMM + fused gather, sequential LSTM
// steps as separate graph-captured launches.
// ---------------------------------------------------------------------------

#define NN 50000
#define KK 16
#define EE (NN * KK)
#define CC 128
#define JKH 192

// ---------------- static device scratch (no allocations allowed) -----------
__device__ int   d_src[EE];
__device__ int   d_is64;
__device__ float d_agg[NN * CC];
__device__ float d_h1[NN * CC];
__device__ float d_h2[NN * CC];
__device__ float d_h3[NN * CC];
__device__ float d_hA[NN * CC];
__device__ float d_cA[NN * CC];
__device__ float d_hzero[NN * JKH];           // all-zero h_prev for first steps
__device__ float d_Z[NN * 4 * JKH];           // gate pre-activations (max 768)
__device__ float d_fwd[3 * NN * JKH];
__device__ float d_bwdp[3 * NN * JKH];        // indexed by xs position consumed
__device__ float d_cF[NN * JKH];
__device__ float d_cB[NN * JKH];
__device__ float d_w[NN * 3];

// ---------------- helpers ---------------------------------------------------
__device__ __forceinline__ float sigmoidf_(float x) { return 1.f / (1.f + expf(-x)); }

// ---------------- edge-index dtype probe + convert --------------------------
__global__ void detect_idx_kernel(const void* ei) {
    // one warp: probe first 128 values as int64; if all in [0,N) -> int64 data
    const long long* p = (const long long*)ei;
    int lane = threadIdx.x;
    int ok = 1;
#pragma unroll
    for (int i = 0; i < 4; ++i) {
        long long v = p[lane * 4 + i];
        if (v < 0 || v >= NN) ok = 0;
    }
    unsigned m = __ballot_sync(0xffffffffu, ok);
    if (lane == 0) d_is64 = (m == 0xffffffffu) ? 1 : 0;
}

__global__ void convert_src_kernel(const void* ei) {
    int idx = blockIdx.x * blockDim.x + threadIdx.x;
    if (idx >= EE) return;
    if (d_is64) d_src[idx] = (int)((const long long*)ei)[idx];
    else        d_src[idx] = ((const int*)ei)[idx];
}

// ---------------- zero fill --------------------------------------------------
__global__ void zero_kernel(float* p, int count) {
    int idx = blockIdx.x * blockDim.x + threadIdx.x;
    if (idx < count) p[idx] = 0.f;
}

// ---------------- neighbor aggregations (mean / max over 16 fixed edges) ----
__global__ void agg_mean_kernel(const float* __restrict__ X, float* __restrict__ out) {
    int idx = blockIdx.x * blockDim.x + threadIdx.x;
    if (idx >= NN * CC) return;
    int n = idx >> 7, c = idx & 127;
    const int* s = d_src + n * KK;
    float acc = 0.f;
#pragma unroll
    for (int j = 0; j < KK; ++j) acc += X[(size_t)s[j] * CC + c];
    out[idx] = acc * (1.f / 16.f);
}

__global__ void agg_max_kernel(const float* __restrict__ X, float* __restrict__ out) {
    int idx = blockIdx.x * blockDim.x + threadIdx.x;
    if (idx >= NN * CC) return;
    int n = idx >> 7, c = idx & 127;
    const int* s = d_src + n * KK;
    float acc = -INFINITY;
#pragma unroll
    for (int j = 0; j < KK; ++j) acc = fmaxf(acc, X[(size_t)s[j] * CC + c]);
    out[idx] = acc;   // every node has 16 in-edges -> always finite
}

// ---------------- fused dual GEMM: C = act(A@W1^T + B@W2^T + b1) ------------
// A rows optionally gathered: rowA = gidx[row*gstride]. K1 = A width, K2 = B width.
// Tiles: 64 (M) x 64 (N) x 32 (K), 256 threads, 4x4 register blocking.
__global__ void dual_gemm_kernel(
    const float* __restrict__ A, const float* __restrict__ B,
    const float* __restrict__ W1, const float* __restrict__ W2,
    const float* __restrict__ b1,
    float* __restrict__ Cout,
    int M, int Nc, int K1, int K2,
    const int* __restrict__ gidx, int gstride,
    int do_relu)
{
    __shared__ __align__(16) float As[32][68];
    __shared__ __align__(16) float Bs[32][68];
    int tid = threadIdx.x;
    int tx = tid & 15, ty = tid >> 4;
    int rowBase = blockIdx.x * 64;
    int colBase = blockIdx.y * 64;
    int Ktot = K1 + K2;

    float acc[4][4];
#pragma unroll
    for (int i = 0; i < 4; ++i)
#pragma unroll
        for (int j = 0; j < 4; ++j) acc[i][j] = 0.f;

    for (int kk = 0; kk < Ktot; kk += 32) {
        // load A tile (64 rows x 32 k), transposed into As[k][m]
#pragma unroll
        for (int u = 0; u < 8; ++u) {
            int e = tid + u * 256;
            int m = e >> 5, k = e & 31;
            int row = rowBase + m;
            int kg = kk + k;
            float v = 0.f;
            if (row < M) {
                if (kg < K1) {
                    int ar = gidx ? gidx[row * gstride] : row;
                    v = A[(size_t)ar * K1 + kg];
                } else {
                    v = B[(size_t)row * K2 + (kg - K1)];
                }
            }
            As[k][m] = v;
        }
        // load W tile (64 cols x 32 k) into Bs[k][n]; Nc % 64 == 0 always
#pragma unroll
        for (int u = 0; u < 8; ++u) {
            int e = tid + u * 256;
            int n = e >> 5, k = e & 31;
            int col = colBase + n;
            int kg = kk + k;
            float v;
            if (kg < K1) v = W1[(size_t)col * K1 + kg];
            else         v = W2[(size_t)col * K2 + (kg - K1)];
            Bs[k][n] = v;
        }
        __syncthreads();
#pragma unroll
        for (int k = 0; k < 32; ++k) {
            float4 av = *(const float4*)&As[k][ty * 4];
            float4 bv = *(const float4*)&Bs[k][tx * 4];
            float a0[4] = {av.x, av.y, av.z, av.w};
            float b0[4] = {bv.x, bv.y, bv.z, bv.w};
#pragma unroll
            for (int i = 0; i < 4; ++i)
#pragma unroll
                for (int j = 0; j < 4; ++j)
                    acc[i][j] = fmaf(a0[i], b0[j], acc[i][j]);
        }
        __syncthreads();
    }

#pragma unroll
    for (int i = 0; i < 4; ++i) {
        int row = rowBase + ty * 4 + i;
        if (row >= M) continue;
#pragma unroll
        for (int j = 0; j < 4; ++j) {
            int col = colBase + tx * 4 + j;
            float v = acc[i][j];
            if (b1) v += b1[col];
            if (do_relu) v = fmaxf(v, 0.f);
            Cout[(size_t)row * Nc + col] = v;
        }
    }
}

// ---------------- LSTM gate nonlinearity + state update ---------------------
// Z layout [N][4H] gate order i,f,g,o (torch). h_out may alias nothing special.
__global__ void lstm_gates_kernel(
    const float* __restrict__ Z,
    const float* __restrict__ bih, const float* __restrict__ bhh,
    float* __restrict__ h_out, float* __restrict__ c_st,
    int H, int first)
{
    int idx = blockIdx.x * blockDim.x + threadIdx.x;
    if (idx >= NN * H) return;
    int n = idx / H, c = idx - n * H;
    const float* zr = Z + (size_t)n * 4 * H;
    float zi = zr[c]         + bih[c]         + bhh[c];
    float zf = zr[H + c]     + bih[H + c]     + bhh[H + c];
    float zg = zr[2 * H + c] + bih[2 * H + c] + bhh[2 * H + c];
    float zo = zr[3 * H + c] + bih[3 * H + c] + bhh[3 * H + c];
    float ig = sigmoidf_(zi);
    float fg = sigmoidf_(zf);
    float gg = tanhf(zg);
    float og = sigmoidf_(zo);
    float cold = first ? 0.f : c_st[idx];
    float cn = fg * cold + ig * gg;
    c_st[idx] = cn;
    h_out[idx] = og * tanhf(cn);
}

// ---------------- JK attention scores + softmax (one warp per node) ---------
__global__ void jk_score_kernel(const float* __restrict__ attw,
                                const float* __restrict__ attb,
                                float* __restrict__ wout)
{
    int gtid = blockIdx.x * blockDim.x + threadIdx.x;
    int node = gtid >> 5;
    int lane = gtid & 31;
    if (node >= NN) return;
    float sc[3];
#pragma unroll
    for (int t = 0; t < 3; ++t) {
        const float* f = d_fwd  + (size_t)t * NN * JKH + (size_t)node * JKH;
        const float* b = d_bwdp + (size_t)t * NN * JKH + (size_t)node * JKH;
        float s = 0.f;
        for (int k = lane; k < JKH; k += 32)
            s += f[k] * attw[k] + b[k] * attw[JKH + k];
#pragma unroll
        for (int off = 16; off > 0; off >>= 1)
            s += __shfl_xor_sync(0xffffffffu, s, off);
        sc[t] = s + attb[0];
    }
    if (lane == 0) {
        float m = fmaxf(sc[0], fmaxf(sc[1], sc[2]));
        float e0 = expf(sc[0] - m), e1 = expf(sc[1] - m), e2 = expf(sc[2] - m);
        float inv = 1.f / (e0 + e1 + e2);
        wout[node * 3 + 0] = e0 * inv;
        wout[node * 3 + 1] = e1 * inv;
        wout[node * 3 + 2] = e2 * inv;
    }
}

__global__ void jk_combine_kernel(float* __restrict__ out) {
    int idx = blockIdx.x * blockDim.x + threadIdx.x;
    if (idx >= NN * CC) return;
    int n = idx >> 7;
    float w0 = d_w[n * 3 + 0], w1 = d_w[n * 3 + 1], w2 = d_w[n * 3 + 2];
    out[idx] = w0 * d_h1[idx] + w1 * d_h2[idx] + w2 * d_h3[idx];
}

// ---------------------------------------------------------------------------
static inline int cdiv(int a, int b) { return (a + b - 1) / b; }

extern "C" void kernel_launch(void* const* d_in, const int* in_sizes, int n_in,
                              void* d_out, int out_size)
{
    // ---- identify inputs by size (robust to dict-order vs signature-order)
    const void* ei = nullptr;
    const float* x = nullptr;
    const float* wp[23];
    int wcount = 0;
    for (int i = 0; i < n_in; ++i) {
        if (in_sizes[i] == 2 * EE)           ei = d_in[i];
        else if (in_sizes[i] == NN * CC)     x  = (const float*)d_in[i];
        else if (wcount < 23)                wp[wcount++] = (const float*)d_in[i];
    }
    // order: Wl1,bl1,Wr1, Wl2,bl2,Wr2, Wl3,bl3,Wr3,
    //        Wih_a,Whh_a,bih_a,bhh_a,
    //        Wih_f,Whh_f,bih_f,bhh_f, Wih_b,Whh_b,bih_b,bhh_b, att_w,att_b
    const float *Wl1 = wp[0],  *bl1 = wp[1],  *Wr1 = wp[2];
    const float *Wl2 = wp[3],  *bl2 = wp[4],  *Wr2 = wp[5];
    const float *Wl3 = wp[6],  *bl3 = wp[7],  *Wr3 = wp[8];
    const float *Wih_a = wp[9],  *Whh_a = wp[10], *bih_a = wp[11], *bhh_a = wp[12];
    const float *Wih_f = wp[13], *Whh_f = wp[14], *bih_f = wp[15], *bhh_f = wp[16];
    const float *Wih_b = wp[17], *Whh_b = wp[18], *bih_b = wp[19], *bhh_b = wp[20];
    const float *att_w = wp[21], *att_b = wp[22];

    // ---- device scratch addresses
    float *agg, *h1, *h2, *h3, *hA, *cA, *hz, *Z, *fwd, *bwdp, *cF, *cB, *wbuf;
    int* srcp;
    cudaGetSymbolAddress((void**)&srcp, d_src);
    cudaGetSymbolAddress((void**)&agg,  d_agg);
    cudaGetSymbolAddress((void**)&h1,   d_h1);
    cudaGetSymbolAddress((void**)&h2,   d_h2);
    cudaGetSymbolAddress((void**)&h3,   d_h3);
    cudaGetSymbolAddress((void**)&hA,   d_hA);
    cudaGetSymbolAddress((void**)&cA,   d_cA);
    cudaGetSymbolAddress((void**)&hz,   d_hzero);
    cudaGetSymbolAddress((void**)&Z,    d_Z);
    cudaGetSymbolAddress((void**)&fwd,  d_fwd);
    cudaGetSymbolAddress((void**)&bwdp, d_bwdp);
    cudaGetSymbolAddress((void**)&cF,   d_cF);
    cudaGetSymbolAddress((void**)&cB,   d_cB);
    cudaGetSymbolAddress((void**)&wbuf, d_w);

    float* out = (float*)d_out;

    const int NC_THREADS = cdiv(NN * CC, 256);
    dim3 g128(cdiv(NN, 64), 128 / 64);
    dim3 g512(cdiv(NN, 64), 512 / 64);
    dim3 g768(cdiv(NN, 64), 768 / 64);

    // ---- edge index normalize
    detect_idx_kernel<<<1, 32>>>(ei);
    convert_src_kernel<<<cdiv(EE, 256), 256>>>(ei);

    // ---- layer 1: mean SAGE + relu
    agg_mean_kernel<<<NC_THREADS, 256>>>(x, agg);
    dual_gemm_kernel<<<g128, 256>>>(agg, x, Wl1, Wr1, bl1, h1,
                                    NN, 128, 128, 128, nullptr, 0, 1);

    // ---- layer 2: max SAGE + relu
    agg_max_kernel<<<NC_THREADS, 256>>>(h1, agg);
    dual_gemm_kernel<<<g128, 256>>>(agg, h1, Wl2, Wr2, bl2, h2,
                                    NN, 128, 128, 128, nullptr, 0, 1);

    // ---- layer 3: LSTM aggregation over the 16 neighbors (sequential steps)
    zero_kernel<<<NC_THREADS, 256>>>(hA, NN * CC);
    for (int t = 0; t < KK; ++t) {
        // Z = h2[src[16i+t]] @ Wih_a^T + hA @ Whh_a^T
        dual_gemm_kernel<<<g512, 256>>>(h2, hA, Wih_a, Whh_a, nullptr, Z,
                                        NN, 512, 128, 128, srcp + t, KK, 0);
        lstm_gates_kernel<<<NC_THREADS, 256>>>(Z, bih_a, bhh_a, hA, cA, 128, t == 0);
    }
    dual_gemm_kernel<<<g128, 256>>>(hA, h2, Wl3, Wr3, bl3, h3,
                                    NN, 128, 128, 128, nullptr, 0, 0);

    // ---- JumpingKnowledge bi-LSTM over [h1,h2,h3]
    zero_kernel<<<cdiv(NN * JKH, 256), 256>>>(hz, NN * JKH);
    const float* xs[3] = {h1, h2, h3};
    for (int t = 0; t < 3; ++t) {
        // forward: consumes xs[t]
        const float* hprevF = (t == 0) ? hz : (fwd + (size_t)(t - 1) * NN * JKH);
        dual_gemm_kernel<<<g768, 256>>>(xs[t], hprevF, Wih_f, Whh_f, nullptr, Z,
                                        NN, 768, 128, JKH, nullptr, 0, 0);
        lstm_gates_kernel<<<cdiv(NN * JKH, 256), 256>>>(
            Z, bih_f, bhh_f, fwd + (size_t)t * NN * JKH, cF, JKH, t == 0);
        // backward: consumes xs[2-t]; state written at position it consumed
        const float* hprevB = (t == 0) ? hz : (bwdp + (size_t)(3 - t) * NN * JKH);
        dual_gemm_kernel<<<g768, 256>>>(xs[2 - t], hprevB, Wih_b, Whh_b, nullptr, Z,
                                        NN, 768, 128, JKH, nullptr, 0, 0);
        lstm_gates_kernel<<<cdiv(NN * JKH, 256), 256>>>(
            Z, bih_b, bhh_b, bwdp + (size_t)(2 - t) * NN * JKH, cB, JKH, t == 0);
    }

    // ---- attention + combine
    jk_score_kernel<<<cdiv(NN * 32, 256), 256>>>(att_w, att_b, wbuf);
    jk_combine_kernel<<<NC_THREADS, 256>>>(out);

    (void)out_size;
}

// round 2
// speedup vs baseline: 4.2566x; 4.2566x over previous
#include <cuda_runtime.h>
#include <math.h>
#include <stdint.h>

// ---------------------------------------------------------------------------
// GraphSAGE (mean -> max -> lstm aggr -> JK bi-LSTM), N=50000, K=16, C=128.
// Round 2: tf32 mma.sync tensor-core GEMM + hoisted LSTM input projections.
// ---------------------------------------------------------------------------

#define NN 50000
#define KK 16
#define EE (NN * KK)
#define CC 128
#define JKH 192

// ---------------- static device scratch -------------------------------------
__device__ int   d_src[EE];
__device__ int   d_is64;
__device__ float d_agg[NN * CC];
__device__ float d_xcat[3 * NN * CC];          // h1 | h2 | h3 (contiguous)
__device__ float d_hA[NN * CC];
__device__ float d_cA[NN * CC];
__device__ float d_Pa[NN * 512];               // h2 @ Wih_a^T
__device__ float d_Pf[3 * NN * 768];           // xcat @ Wih_f^T
__device__ float d_Pb[3 * NN * 768];           // xcat @ Wih_b^T
__device__ float d_Z[NN * 768];                // recurrent gate pre-acts
__device__ float d_fwd[3 * NN * JKH];
__device__ float d_bwdp[3 * NN * JKH];         // indexed by xs position consumed
__device__ float d_cF[NN * JKH];
__device__ float d_cB[NN * JKH];
__device__ float d_w[NN * 3];

__device__ __forceinline__ float sigmoidf_(float x) { return 1.f / (1.f + expf(-x)); }

__device__ __forceinline__ uint32_t f2tf32(float f) {
    uint32_t u;
    asm("cvt.rna.tf32.f32 %0, %1;" : "=r"(u) : "f"(f));
    return u;
}

// ---------------- edge-index dtype probe + convert --------------------------
__global__ void detect_idx_kernel(const void* ei) {
    const long long* p = (const long long*)ei;
    int lane = threadIdx.x;
    int ok = 1;
#pragma unroll
    for (int i = 0; i < 4; ++i) {
        long long v = p[lane * 4 + i];
        if (v < 0 || v >= NN) ok = 0;
    }
    unsigned m = __ballot_sync(0xffffffffu, ok);
    if (lane == 0) d_is64 = (m == 0xffffffffu) ? 1 : 0;
}

__global__ void convert_src_kernel(const void* ei) {
    int idx = blockIdx.x * blockDim.x + threadIdx.x;
    if (idx >= EE) return;
    if (d_is64) d_src[idx] = (int)((const long long*)ei)[idx];
    else        d_src[idx] = ((const int*)ei)[idx];
}

// ---------------- neighbor aggregations -------------------------------------
__global__ void agg_mean_kernel(const float* __restrict__ X, float* __restrict__ out) {
    int idx = blockIdx.x * blockDim.x + threadIdx.x;
    if (idx >= NN * CC) return;
    int n = idx >> 7, c = idx & 127;
    const int* s = d_src + n * KK;
    float acc = 0.f;
#pragma unroll
    for (int j = 0; j < KK; ++j) acc += X[(size_t)s[j] * CC + c];
    out[idx] = acc * (1.f / 16.f);
}

__global__ void agg_max_kernel(const float* __restrict__ X, float* __restrict__ out) {
    int idx = blockIdx.x * blockDim.x + threadIdx.x;
    if (idx >= NN * CC) return;
    int n = idx >> 7, c = idx & 127;
    const int* s = d_src + n * KK;
    float acc = -INFINITY;
#pragma unroll
    for (int j = 0; j < KK; ++j) acc = fmaxf(acc, X[(size_t)s[j] * CC + c]);
    out[idx] = acc;
}

// ---------------- tf32 tensor-core GEMM -------------------------------------
// Cout[M x Nc] = act( A[M x K1] @ W1^T + B2[M x K2] @ W2^T + bias )
// K-concat trick: virtual K = K1 + K2, tile BK=16 divides K1 (all our K1 % 16 == 0).
// Tiles: BM=128, BN=64, BK=16; 8 warps (4 M x 2 N); warp tile 32x32;
// mma.m16n8k8.tf32: per warp 2 mtiles x 4 ntiles x 2 ktiles per BK.
#define BM 128
#define BN 64
#define BK 16
#define ASTR 20   // As row stride (words): conflict-free fragment loads
#define BSTR 72   // Bs row stride (words)

__global__ __launch_bounds__(256) void tf32_gemm_kernel(
    const float* __restrict__ A, const float* __restrict__ B2,
    const float* __restrict__ W1, const float* __restrict__ W2,
    const float* __restrict__ bias, float* __restrict__ Cout,
    int M, int Nc, int K1, int K2, int do_relu)
{
    __shared__ __align__(16) uint32_t As[2][BM][ASTR];
    __shared__ __align__(16) uint32_t Bs[2][BK][BSTR];

    const int tid  = threadIdx.x;
    const int wid  = tid >> 5;
    const int lane = tid & 31;
    const int grp  = lane >> 2;     // 0..7
    const int tig  = lane & 3;      // 0..3
    const int warpM = wid >> 1;     // 0..3
    const int warpN = wid & 1;      // 0..1

    const int rowBase = blockIdx.x * BM;
    const int colBase = blockIdx.y * BN;
    const int Ktot = K1 + K2;

    // loader indexing
    const int arow0 = (tid >> 2);           // A: e = tid + u*256 -> row = e>>2
    const int akq   = (tid & 3) * 4;        // k offset within tile
    const int wrow  = (tid >> 2);           // W: n within tile
    const int wkq   = (tid & 3) * 4;

    float c[2][4][4];
#pragma unroll
    for (int mt = 0; mt < 2; ++mt)
#pragma unroll
        for (int nt = 0; nt < 4; ++nt)
#pragma unroll
            for (int i = 0; i < 4; ++i) c[mt][nt][i] = 0.f;

    float4 av[2], wv;

    // ---- fetch tile at kk into registers
    auto fetch = [&](int kk) {
        const float* asrc; const float* wsrc; int ld, kb;
        if (kk < K1) { asrc = A;  wsrc = W1; ld = K1; kb = kk; }
        else         { asrc = B2; wsrc = W2; ld = K2; kb = kk - K1; }
#pragma unroll
        for (int u = 0; u < 2; ++u) {
            int row = rowBase + arow0 + u * 64;
            if (row < M)
                av[u] = *(const float4*)(asrc + (size_t)row * ld + kb + akq);
            else
                av[u] = make_float4(0.f, 0.f, 0.f, 0.f);
        }
        wv = *(const float4*)(wsrc + (size_t)(colBase + wrow) * ld + kb + wkq);
    };

    auto store = [&](int buf) {
        uint4 u0, u1;
        u0.x = f2tf32(av[0].x); u0.y = f2tf32(av[0].y); u0.z = f2tf32(av[0].z); u0.w = f2tf32(av[0].w);
        u1.x = f2tf32(av[1].x); u1.y = f2tf32(av[1].y); u1.z = f2tf32(av[1].z); u1.w = f2tf32(av[1].w);
        *(uint4*)&As[buf][arow0][akq]      = u0;
        *(uint4*)&As[buf][arow0 + 64][akq] = u1;
        Bs[buf][wkq + 0][wrow] = f2tf32(wv.x);
        Bs[buf][wkq + 1][wrow] = f2tf32(wv.y);
        Bs[buf][wkq + 2][wrow] = f2tf32(wv.z);
        Bs[buf][wkq + 3][wrow] = f2tf32(wv.w);
    };

    fetch(0);
    store(0);
    __syncthreads();

    const int nk = Ktot / BK;
    int buf = 0;
    for (int it = 0; it < nk; ++it) {
        if (it + 1 < nk) fetch((it + 1) * BK);

        // compute from As[buf], Bs[buf]
#pragma unroll
        for (int kt = 0; kt < 2; ++kt) {
            const int k0 = kt * 8;
            uint32_t af[2][4], bf[4][2];
#pragma unroll
            for (int mt = 0; mt < 2; ++mt) {
                int m = warpM * 32 + mt * 16;
                af[mt][0] = As[buf][m + grp][k0 + tig];
                af[mt][1] = As[buf][m + 8 + grp][k0 + tig];
                af[mt][2] = As[buf][m + grp][k0 + tig + 4];
                af[mt][3] = As[buf][m + 8 + grp][k0 + tig + 4];
            }
#pragma unroll
            for (int nt = 0; nt < 4; ++nt) {
                int n = warpN * 32 + nt * 8;
                bf[nt][0] = Bs[buf][k0 + tig][n + grp];
                bf[nt][1] = Bs[buf][k0 + tig + 4][n + grp];
            }
#pragma unroll
            for (int mt = 0; mt < 2; ++mt)
#pragma unroll
                for (int nt = 0; nt < 4; ++nt) {
                    asm volatile(
                        "mma.sync.aligned.m16n8k8.row.col.f32.tf32.tf32.f32 "
                        "{%0,%1,%2,%3}, {%4,%5,%6,%7}, {%8,%9}, {%0,%1,%2,%3};\n"
                        : "+f"(c[mt][nt][0]), "+f"(c[mt][nt][1]),
                          "+f"(c[mt][nt][2]), "+f"(c[mt][nt][3])
                        : "r"(af[mt][0]), "r"(af[mt][1]), "r"(af[mt][2]), "r"(af[mt][3]),
                          "r"(bf[nt][0]), "r"(bf[nt][1]));
                }
        }

        if (it + 1 < nk) {
            __syncthreads();
            store(buf ^ 1);
            __syncthreads();
            buf ^= 1;
        }
    }

    // ---- epilogue
#pragma unroll
    for (int mt = 0; mt < 2; ++mt) {
#pragma unroll
        for (int nt = 0; nt < 4; ++nt) {
            int col = colBase + warpN * 32 + nt * 8 + tig * 2;
            float b0 = bias ? bias[col] : 0.f;
            float b1 = bias ? bias[col + 1] : 0.f;
            int r0 = rowBase + warpM * 32 + mt * 16 + grp;
            int r1 = r0 + 8;
            float v0 = c[mt][nt][0] + b0, v1 = c[mt][nt][1] + b1;
            float v2 = c[mt][nt][2] + b0, v3 = c[mt][nt][3] + b1;
            if (do_relu) {
                v0 = fmaxf(v0, 0.f); v1 = fmaxf(v1, 0.f);
                v2 = fmaxf(v2, 0.f); v3 = fmaxf(v3, 0.f);
            }
            if (r0 < M) *(float2*)(Cout + (size_t)r0 * Nc + col) = make_float2(v0, v1);
            if (r1 < M) *(float2*)(Cout + (size_t)r1 * Nc + col) = make_float2(v2, v3);
        }
    }
}

// ---------------- LSTM gates: z = Zrec + P[gathered] + biases ---------------
__global__ void lstm_gates_kernel(
    const float* __restrict__ Zrec,       // may be null (first step)
    const float* __restrict__ P,          // precomputed input projection
    const int* __restrict__ src, int t,   // src!=null -> gather row src[n*16+t]
    const float* __restrict__ bih, const float* __restrict__ bhh,
    float* __restrict__ h_out, float* __restrict__ c_st,
    int H, int first)
{
    int idx = blockIdx.x * blockDim.x + threadIdx.x;
    if (idx >= NN * H) return;
    int n = idx / H, cc = idx - n * H;
    int pn = src ? src[n * KK + t] : n;
    const float* pr = P + (size_t)pn * 4 * H;
    float z[4];
#pragma unroll
    for (int g = 0; g < 4; ++g) {
        float v = pr[g * H + cc] + bih[g * H + cc] + bhh[g * H + cc];
        if (Zrec) v += Zrec[(size_t)n * 4 * H + g * H + cc];
        z[g] = v;
    }
    float ig = sigmoidf_(z[0]);
    float fg = sigmoidf_(z[1]);
    float gg = tanhf(z[2]);
    float og = sigmoidf_(z[3]);
    float cold = first ? 0.f : c_st[idx];
    float cn = fg * cold + ig * gg;
    c_st[idx] = cn;
    h_out[idx] = og * tanhf(cn);
}

// ---------------- JK attention scores + softmax -----------------------------
__global__ void jk_score_kernel(const float* __restrict__ attw,
                                const float* __restrict__ attb,
                                float* __restrict__ wout)
{
    int gtid = blockIdx.x * blockDim.x + threadIdx.x;
    int node = gtid >> 5;
    int lane = gtid & 31;
    if (node >= NN) return;
    float sc[3];
#pragma unroll
    for (int t = 0; t < 3; ++t) {
        const float* f = d_fwd  + (size_t)t * NN * JKH + (size_t)node * JKH;
        const float* b = d_bwdp + (size_t)t * NN * JKH + (size_t)node * JKH;
        float s = 0.f;
        for (int k = lane; k < JKH; k += 32)
            s += f[k] * attw[k] + b[k] * attw[JKH + k];
#pragma unroll
        for (int off = 16; off > 0; off >>= 1)
            s += __shfl_xor_sync(0xffffffffu, s, off);
        sc[t] = s + attb[0];
    }
    if (lane == 0) {
        float m = fmaxf(sc[0], fmaxf(sc[1], sc[2]));
        float e0 = expf(sc[0] - m), e1 = expf(sc[1] - m), e2 = expf(sc[2] - m);
        float inv = 1.f / (e0 + e1 + e2);
        wout[node * 3 + 0] = e0 * inv;
        wout[node * 3 + 1] = e1 * inv;
        wout[node * 3 + 2] = e2 * inv;
    }
}

__global__ void jk_combine_kernel(float* __restrict__ out) {
    int idx = blockIdx.x * blockDim.x + threadIdx.x;
    if (idx >= NN * CC) return;
    int n = idx >> 7;
    float w0 = d_w[n * 3 + 0], w1 = d_w[n * 3 + 1], w2 = d_w[n * 3 + 2];
    out[idx] = w0 * d_xcat[idx] + w1 * d_xcat[NN * CC + idx] + w2 * d_xcat[2 * NN * CC + idx];
}

// ---------------------------------------------------------------------------
static inline int cdiv(int a, int b) { return (a + b - 1) / b; }

extern "C" void kernel_launch(void* const* d_in, const int* in_sizes, int n_in,
                              void* d_out, int out_size)
{
    // ---- identify inputs by size
    const void* ei = nullptr;
    const float* x = nullptr;
    const float* wp[23];
    int wcount = 0;
    for (int i = 0; i < n_in; ++i) {
        if (in_sizes[i] == 2 * EE)       ei = d_in[i];
        else if (in_sizes[i] == NN * CC) x  = (const float*)d_in[i];
        else if (wcount < 23)            wp[wcount++] = (const float*)d_in[i];
    }
    const float *Wl1 = wp[0],  *bl1 = wp[1],  *Wr1 = wp[2];
    const float *Wl2 = wp[3],  *bl2 = wp[4],  *Wr2 = wp[5];
    const float *Wl3 = wp[6],  *bl3 = wp[7],  *Wr3 = wp[8];
    const float *Wih_a = wp[9],  *Whh_a = wp[10], *bih_a = wp[11], *bhh_a = wp[12];
    const float *Wih_f = wp[13], *Whh_f = wp[14], *bih_f = wp[15], *bhh_f = wp[16];
    const float *Wih_b = wp[17], *Whh_b = wp[18], *bih_b = wp[19], *bhh_b = wp[20];
    const float *att_w = wp[21], *att_b = wp[22];

    float *agg, *xcat, *hA, *cA, *Pa, *Pf, *Pb, *Z, *fwd, *bwdp, *cF, *cB, *wbuf;
    int* srcp;
    cudaGetSymbolAddress((void**)&srcp, d_src);
    cudaGetSymbolAddress((void**)&agg,  d_agg);
    cudaGetSymbolAddress((void**)&xcat, d_xcat);
    cudaGetSymbolAddress((void**)&hA,   d_hA);
    cudaGetSymbolAddress((void**)&cA,   d_cA);
    cudaGetSymbolAddress((void**)&Pa,   d_Pa);
    cudaGetSymbolAddress((void**)&Pf,   d_Pf);
    cudaGetSymbolAddress((void**)&Pb,   d_Pb);
    cudaGetSymbolAddress((void**)&Z,    d_Z);
    cudaGetSymbolAddress((void**)&fwd,  d_fwd);
    cudaGetSymbolAddress((void**)&bwdp, d_bwdp);
    cudaGetSymbolAddress((void**)&cF,   d_cF);
    cudaGetSymbolAddress((void**)&cB,   d_cB);
    cudaGetSymbolAddress((void**)&wbuf, d_w);

    float* h1 = xcat;
    float* h2 = xcat + NN * CC;
    float* h3 = xcat + 2 * NN * CC;
    float* out = (float*)d_out;

    const int NC_BLK  = cdiv(NN * CC, 256);
    const int NJ_BLK  = cdiv(NN * JKH, 256);
    dim3 g128(cdiv(NN, BM), 128 / BN);
    dim3 g512(cdiv(NN, BM), 512 / BN);
    dim3 g768(cdiv(NN, BM), 768 / BN);
    dim3 g768x3(cdiv(3 * NN, BM), 768 / BN);

    // ---- edge index normalize
    detect_idx_kernel<<<1, 32>>>(ei);
    convert_src_kernel<<<cdiv(EE, 256), 256>>>(ei);

    // ---- layer 1: mean SAGE + relu
    agg_mean_kernel<<<NC_BLK, 256>>>(x, agg);
    tf32_gemm_kernel<<<g128, 256>>>(agg, x, Wl1, Wr1, bl1, h1,
                                    NN, 128, 128, 128, 1);

    // ---- layer 2: max SAGE + relu
    agg_max_kernel<<<NC_BLK, 256>>>(h1, agg);
    tf32_gemm_kernel<<<g128, 256>>>(agg, h1, Wl2, Wr2, bl2, h2,
                                    NN, 128, 128, 128, 1);

    // ---- layer 3: LSTM aggregation (input projection hoisted)
    tf32_gemm_kernel<<<g512, 256>>>(h2, nullptr, Wih_a, nullptr, nullptr, Pa,
                                    NN, 512, 128, 0, 0);
    for (int t = 0; t < KK; ++t) {
        const float* zr = nullptr;
        if (t > 0) {
            tf32_gemm_kernel<<<g512, 256>>>(hA, nullptr, Whh_a, nullptr, nullptr, Z,
                                            NN, 512, 128, 0, 0);
            zr = Z;
        }
        lstm_gates_kernel<<<NC_BLK, 256>>>(zr, Pa, srcp, t, bih_a, bhh_a,
                                           hA, cA, 128, t == 0);
    }
    tf32_gemm_kernel<<<g128, 256>>>(hA, h2, Wl3, Wr3, bl3, h3,
                                    NN, 128, 128, 128, 0);

    // ---- JK bi-LSTM: batched input projections over xcat = [h1;h2;h3]
    tf32_gemm_kernel<<<g768x3, 256>>>(xcat, nullptr, Wih_f, nullptr, nullptr, Pf,
                                      3 * NN, 768, 128, 0, 0);
    tf32_gemm_kernel<<<g768x3, 256>>>(xcat, nullptr, Wih_b, nullptr, nullptr, Pb,
                                      3 * NN, 768, 128, 0, 0);

    for (int t = 0; t < 3; ++t) {
        // forward consumes xs[t]
        const float* zrF = nullptr;
        if (t > 0) {
            tf32_gemm_kernel<<<g768, 256>>>(fwd + (size_t)(t - 1) * NN * JKH, nullptr,
                                            Whh_f, nullptr, nullptr, Z,
                                            NN, 768, JKH, 0, 0);
            zrF = Z;
        }
        lstm_gates_kernel<<<NJ_BLK, 256>>>(zrF, Pf + (size_t)t * NN * 768, nullptr, 0,
                                           bih_f, bhh_f,
                                           fwd + (size_t)t * NN * JKH, cF, JKH, t == 0);
        // backward consumes xs[2-t]; state stored at position consumed
        const float* zrB = nullptr;
        if (t > 0) {
            tf32_gemm_kernel<<<g768, 256>>>(bwdp + (size_t)(3 - t) * NN * JKH, nullptr,
                                            Whh_b, nullptr, nullptr, Z,
                                            NN, 768, JKH, 0, 0);
            zrB = Z;
        }
        lstm_gates_kernel<<<NJ_BLK, 256>>>(zrB, Pb + (size_t)(2 - t) * NN * 768, nullptr, 0,
                                           bih_b, bhh_b,
                                           bwdp + (size_t)(2 - t) * NN * JKH, cB, JKH, t == 0);
    }

    // ---- attention + combine
    jk_score_kernel<<<cdiv(NN * 32, 256), 256>>>(att_w, att_b, wbuf);
    jk_combine_kernel<<<NC_BLK, 256>>>(out);

    (void)out_size;
}

// round 4
// speedup vs baseline: 6.2874x; 1.4771x over previous
#include <cuda_runtime.h>
#include <math.h>
#include <stdint.h>

// ---------------------------------------------------------------------------
// GraphSAGE (mean -> max -> lstm aggr -> JK bi-LSTM), N=50000, K=16, C=128.
// Round 4 (= round 3 resubmit after infra failure): cp.async 3-stage tf32 mma
// pipeline (BM128 BN128 BK32), pre-rounded tf32 operands, float4 gates kernel.
// ---------------------------------------------------------------------------

#define NN 50000
#define KK 16
#define EE (NN * KK)
#define CC 128
#define JKH 192

#define BM 128
#define BN 128
#define BKT 32
#define ASTR 36                   // words per smem row (32 + 4 pad, 16B aligned)
#define AW (BM * ASTR)            // 4608 words
#define BW (BN * ASTR)            // 4608 words
#define SW (AW + BW)              // stage words
#define SMEM_BYTES (3 * SW * 4)   // 110592

// ---------------- static device scratch -------------------------------------
__device__ int   d_src[EE];
__device__ int   d_is64;
__device__ float d_xr[NN * CC];                 // tf32-rounded x
__device__ float d_agg[NN * CC];
__device__ float d_xcat[3 * NN * CC];           // h1 | h2 | h3
__device__ float d_hA[NN * CC];
__device__ float d_cA[NN * CC];
__device__ float d_Pa[NN * 512];
__device__ float d_Pf[3 * NN * 768];
__device__ float d_Pb[3 * NN * 768];
__device__ float d_Z[NN * 768];
__device__ float d_fwd[3 * NN * JKH];
__device__ float d_bwdp[3 * NN * JKH];
__device__ float d_cF[NN * JKH];
__device__ float d_cB[NN * JKH];
__device__ float d_w[NN * 3];
__device__ float d_wr[720896];                  // rounded weights arena

__device__ __forceinline__ float sigmoidf_(float x) { return 1.f / (1.f + expf(-x)); }

__device__ __forceinline__ uint32_t f2tf32(float f) {
    uint32_t u;
    asm("cvt.rna.tf32.f32 %0, %1;" : "=r"(u) : "f"(f));
    return u;
}
__device__ __forceinline__ float roundtf(float f) { return __uint_as_float(f2tf32(f)); }

// ---------------- edge-index dtype probe + convert --------------------------
__global__ void detect_idx_kernel(const void* ei) {
    const long long* p = (const long long*)ei;
    int lane = threadIdx.x;
    int ok = 1;
#pragma unroll
    for (int i = 0; i < 4; ++i) {
        long long v = p[lane * 4 + i];
        if (v < 0 || v >= NN) ok = 0;
    }
    unsigned m = __ballot_sync(0xffffffffu, ok);
    if (lane == 0) d_is64 = (m == 0xffffffffu) ? 1 : 0;
}

__global__ void convert_src_kernel(const void* ei) {
    int idx = blockIdx.x * blockDim.x + threadIdx.x;
    if (idx >= EE) return;
    if (d_is64) d_src[idx] = (int)((const long long*)ei)[idx];
    else        d_src[idx] = ((const int*)ei)[idx];
}

// ---------------- tf32 rounding pass (float4) --------------------------------
__global__ void round_kernel(const float* __restrict__ in, float* __restrict__ out, int n4) {
    int i = blockIdx.x * blockDim.x + threadIdx.x;
    if (i >= n4) return;
    float4 v = ((const float4*)in)[i];
    v.x = roundtf(v.x); v.y = roundtf(v.y); v.z = roundtf(v.z); v.w = roundtf(v.w);
    ((float4*)out)[i] = v;
}

// ---------------- neighbor aggregations (outputs tf32-rounded) ---------------
__global__ void agg_mean_kernel(const float* __restrict__ X, float* __restrict__ out) {
    int idx = blockIdx.x * blockDim.x + threadIdx.x;
    if (idx >= NN * CC) return;
    int n = idx >> 7, c = idx & 127;
    const int* s = d_src + n * KK;
    float acc = 0.f;
#pragma unroll
    for (int j = 0; j < KK; ++j) acc += X[(size_t)s[j] * CC + c];
    out[idx] = roundtf(acc * (1.f / 16.f));
}

__global__ void agg_max_kernel(const float* __restrict__ X, float* __restrict__ out) {
    int idx = blockIdx.x * blockDim.x + threadIdx.x;
    if (idx >= NN * CC) return;
    int n = idx >> 7, c = idx & 127;
    const int* s = d_src + n * KK;
    float acc = -INFINITY;
#pragma unroll
    for (int j = 0; j < KK; ++j) acc = fmaxf(acc, X[(size_t)s[j] * CC + c]);
    out[idx] = roundtf(acc);
}

// ---------------- tf32 tensor-core GEMM, cp.async 3-stage --------------------
// Cout[M x Nc] = act( A[M x K1] @ W1^T + B2[M x K2] @ W2^T + bias )
// All operands pre-rounded to tf32. flags: bit0 relu, bit1 round-output.
__global__ __launch_bounds__(256, 2) void tf32_gemm_kernel(
    const float* __restrict__ A, const float* __restrict__ B2,
    const float* __restrict__ W1, const float* __restrict__ W2,
    const float* __restrict__ bias, float* __restrict__ Cout,
    int M, int Nc, int K1, int K2, int flags)
{
    extern __shared__ __align__(16) float sm[];

    const int tid  = threadIdx.x;
    const int wid  = tid >> 5;
    const int lane = tid & 31;
    const int grp  = lane >> 2;
    const int tig  = lane & 3;
    const int warpM = wid >> 1;     // 0..3 (32 rows each)
    const int warpN = wid & 1;      // 0..1 (64 cols each)

    const int rowBase = blockIdx.x * BM;
    const int colBase = blockIdx.y * BN;
    const int Ktot = K1 + K2;
    const int nk = Ktot / BKT;

    // copy indexing: 1024 chunks of 16B per tile side, 256 threads x 4 passes
    const int cr = tid >> 3;            // row advances by 32 per pass
    const int ck = (tid & 7) * 4;       // k word offset

    float c[2][8][4];
#pragma unroll
    for (int mt = 0; mt < 2; ++mt)
#pragma unroll
        for (int nt = 0; nt < 8; ++nt)
#pragma unroll
            for (int i = 0; i < 4; ++i) c[mt][nt][i] = 0.f;

    auto issue = [&](int it, int s) {
        if (it < nk) {
            int kk = it * BKT;
            const float* asrc; const float* wsrc; int ld, kb;
            if (kk < K1) { asrc = A;  wsrc = W1; ld = K1; kb = kk; }
            else         { asrc = B2; wsrc = W2; ld = K2; kb = kk - K1; }
            float* smA = sm + s * SW;
            float* smB = smA + AW;
#pragma unroll
            for (int p = 0; p < 4; ++p) {
                int r = cr + p * 32;
                int row = rowBase + r;
                int rc = (row < M) ? row : 0;
                uint32_t dst = (uint32_t)__cvta_generic_to_shared(smA + r * ASTR + ck);
                const float* g = asrc + (size_t)rc * ld + kb + ck;
                int sz = (row < M) ? 16 : 0;
                asm volatile("cp.async.cg.shared.global [%0], [%1], 16, %2;\n"
                             :: "r"(dst), "l"(g), "r"(sz));
            }
#pragma unroll
            for (int p = 0; p < 4; ++p) {
                int r = cr + p * 32;
                uint32_t dst = (uint32_t)__cvta_generic_to_shared(smB + r * ASTR + ck);
                const float* g = wsrc + (size_t)(colBase + r) * ld + kb + ck;
                asm volatile("cp.async.cg.shared.global [%0], [%1], 16;\n"
                             :: "r"(dst), "l"(g));
            }
        }
        asm volatile("cp.async.commit_group;\n");
    };

    issue(0, 0);
    issue(1, 1);

    for (int it = 0; it < nk; ++it) {
        asm volatile("cp.async.wait_group 1;\n");
        __syncthreads();

        const int s = it % 3;
        const float* smA = sm + s * SW;
        const float* smB = smA + AW;
        const int m0 = warpM * 32;
        const int n0 = warpN * 64;

#pragma unroll
        for (int kt = 0; kt < 4; ++kt) {
            const int k0 = kt * 8;
            uint32_t af[2][4], bf[8][2];
#pragma unroll
            for (int mt = 0; mt < 2; ++mt) {
                int m = m0 + mt * 16;
                af[mt][0] = __float_as_uint(smA[(m + grp) * ASTR + k0 + tig]);
                af[mt][1] = __float_as_uint(smA[(m + 8 + grp) * ASTR + k0 + tig]);
                af[mt][2] = __float_as_uint(smA[(m + grp) * ASTR + k0 + tig + 4]);
                af[mt][3] = __float_as_uint(smA[(m + 8 + grp) * ASTR + k0 + tig + 4]);
            }
#pragma unroll
            for (int nt = 0; nt < 8; ++nt) {
                int n = n0 + nt * 8;
                bf[nt][0] = __float_as_uint(smB[(n + grp) * ASTR + k0 + tig]);
                bf[nt][1] = __float_as_uint(smB[(n + grp) * ASTR + k0 + tig + 4]);
            }
#pragma unroll
            for (int mt = 0; mt < 2; ++mt)
#pragma unroll
                for (int nt = 0; nt < 8; ++nt) {
                    asm volatile(
                        "mma.sync.aligned.m16n8k8.row.col.f32.tf32.tf32.f32 "
                        "{%0,%1,%2,%3}, {%4,%5,%6,%7}, {%8,%9}, {%0,%1,%2,%3};\n"
                        : "+f"(c[mt][nt][0]), "+f"(c[mt][nt][1]),
                          "+f"(c[mt][nt][2]), "+f"(c[mt][nt][3])
                        : "r"(af[mt][0]), "r"(af[mt][1]), "r"(af[mt][2]), "r"(af[mt][3]),
                          "r"(bf[nt][0]), "r"(bf[nt][1]));
                }
        }
        issue(it + 2, (it + 2) % 3);
    }

    const int do_relu = flags & 1;
    const int do_round = flags & 2;
#pragma unroll
    for (int mt = 0; mt < 2; ++mt) {
#pragma unroll
        for (int nt = 0; nt < 8; ++nt) {
            int col = colBase + warpN * 64 + nt * 8 + tig * 2;
            float b0 = bias ? bias[col] : 0.f;
            float b1 = bias ? bias[col + 1] : 0.f;
            int r0 = rowBase + warpM * 32 + mt * 16 + grp;
            int r1 = r0 + 8;
            float v0 = c[mt][nt][0] + b0, v1 = c[mt][nt][1] + b1;
            float v2 = c[mt][nt][2] + b0, v3 = c[mt][nt][3] + b1;
            if (do_relu) {
                v0 = fmaxf(v0, 0.f); v1 = fmaxf(v1, 0.f);
                v2 = fmaxf(v2, 0.f); v3 = fmaxf(v3, 0.f);
            }
            if (do_round) {
                v0 = roundtf(v0); v1 = roundtf(v1);
                v2 = roundtf(v2); v3 = roundtf(v3);
            }
            if (r0 < M) *(float2*)(Cout + (size_t)r0 * Nc + col) = make_float2(v0, v1);
            if (r1 < M) *(float2*)(Cout + (size_t)r1 * Nc + col) = make_float2(v2, v3);
        }
    }
}

// ---------------- LSTM gates (float4): z = Zrec + P[gathered] + biases -------
__global__ void lstm_gates_kernel(
    const float* __restrict__ Zrec,
    const float* __restrict__ P,
    const int* __restrict__ src, int t,
    const float* __restrict__ bih, const float* __restrict__ bhh,
    float* __restrict__ h_out, float* __restrict__ c_st,
    int H, int first)
{
    int hv = H >> 2;
    int idx = blockIdx.x * blockDim.x + threadIdx.x;
    if (idx >= NN * hv) return;
    int n = idx / hv, q = idx - n * hv;
    int pn = src ? src[n * KK + t] : n;
    const float4* pr = (const float4*)(P + (size_t)pn * 4 * H);
    const float4* zr = Zrec ? (const float4*)(Zrec + (size_t)n * 4 * H) : nullptr;
    const float4* b1 = (const float4*)bih;
    const float4* b2 = (const float4*)bhh;

    float4 z[4];
#pragma unroll
    for (int g = 0; g < 4; ++g) {
        float4 v = pr[g * hv + q];
        float4 a = b1[g * hv + q], b = b2[g * hv + q];
        v.x += a.x + b.x; v.y += a.y + b.y; v.z += a.z + b.z; v.w += a.w + b.w;
        if (zr) {
            float4 u = zr[g * hv + q];
            v.x += u.x; v.y += u.y; v.z += u.z; v.w += u.w;
        }
        z[g] = v;
    }
    float4 cold = first ? make_float4(0.f, 0.f, 0.f, 0.f) : ((float4*)c_st)[idx];
    float4 cn, hn;
#pragma unroll
    for (int e = 0; e < 4; ++e) {
        float zi = (&z[0].x)[e], zf = (&z[1].x)[e], zg = (&z[2].x)[e], zo = (&z[3].x)[e];
        float ig = sigmoidf_(zi), fg = sigmoidf_(zf);
        float gg = tanhf(zg), og = sigmoidf_(zo);
        float cc = fg * (&cold.x)[e] + ig * gg;
        (&cn.x)[e] = cc;
        (&hn.x)[e] = roundtf(og * tanhf(cc));
    }
    ((float4*)c_st)[idx] = cn;
    ((float4*)h_out)[idx] = hn;
}

// ---------------- JK attention scores + softmax ------------------------------
__global__ void jk_score_kernel(const float* __restrict__ attw,
                                const float* __restrict__ attb,
                                float* __restrict__ wout)
{
    int gtid = blockIdx.x * blockDim.x + threadIdx.x;
    int node = gtid >> 5;
    int lane = gtid & 31;
    if (node >= NN) return;
    float sc[3];
#pragma unroll
    for (int t = 0; t < 3; ++t) {
        const float* f = d_fwd  + (size_t)t * NN * JKH + (size_t)node * JKH;
        const float* b = d_bwdp + (size_t)t * NN * JKH + (size_t)node * JKH;
        float s = 0.f;
        for (int k = lane; k < JKH; k += 32)
            s += f[k] * attw[k] + b[k] * attw[JKH + k];
#pragma unroll
        for (int off = 16; off > 0; off >>= 1)
            s += __shfl_xor_sync(0xffffffffu, s, off);
        sc[t] = s + attb[0];
    }
    if (lane == 0) {
        float m = fmaxf(sc[0], fmaxf(sc[1], sc[2]));
        float e0 = expf(sc[0] - m), e1 = expf(sc[1] - m), e2 = expf(sc[2] - m);
        float inv = 1.f / (e0 + e1 + e2);
        wout[node * 3 + 0] = e0 * inv;
        wout[node * 3 + 1] = e1 * inv;
        wout[node * 3 + 2] = e2 * inv;
    }
}

__global__ void jk_combine_kernel(float* __restrict__ out) {
    int idx = blockIdx.x * blockDim.x + threadIdx.x;
    if (idx >= NN * CC) return;
    int n = idx >> 7;
    float w0 = d_w[n * 3 + 0], w1 = d_w[n * 3 + 1], w2 = d_w[n * 3 + 2];
    out[idx] = w0 * d_xcat[idx] + w1 * d_xcat[NN * CC + idx] + w2 * d_xcat[2 * NN * CC + idx];
}

// ---------------------------------------------------------------------------
static inline int cdiv(int a, int b) { return (a + b - 1) / b; }

extern "C" void kernel_launch(void* const* d_in, const int* in_sizes, int n_in,
                              void* d_out, int out_size)
{
    const void* ei = nullptr;
    const float* x = nullptr;
    const float* wp[23];
    int wcount = 0;
    for (int i = 0; i < n_in; ++i) {
        if (in_sizes[i] == 2 * EE)       ei = d_in[i];
        else if (in_sizes[i] == NN * CC) x  = (const float*)d_in[i];
        else if (wcount < 23)            wp[wcount++] = (const float*)d_in[i];
    }
    const float *Wl1 = wp[0],  *bl1 = wp[1],  *Wr1 = wp[2];
    const float *Wl2 = wp[3],  *bl2 = wp[4],  *Wr2 = wp[5];
    const float *Wl3 = wp[6],  *bl3 = wp[7],  *Wr3 = wp[8];
    const float *Wih_a = wp[9],  *Whh_a = wp[10], *bih_a = wp[11], *bhh_a = wp[12];
    const float *Wih_f = wp[13], *Whh_f = wp[14], *bih_f = wp[15], *bhh_f = wp[16];
    const float *Wih_b = wp[17], *Whh_b = wp[18], *bih_b = wp[19], *bhh_b = wp[20];
    const float *att_w = wp[21], *att_b = wp[22];

    float *xr, *agg, *xcat, *hA, *cA, *Pa, *Pf, *Pb, *Z, *fwd, *bwdp, *cF, *cB, *wbuf, *wr;
    int* srcp;
    cudaGetSymbolAddress((void**)&srcp, d_src);
    cudaGetSymbolAddress((void**)&xr,   d_xr);
    cudaGetSymbolAddress((void**)&agg,  d_agg);
    cudaGetSymbolAddress((void**)&xcat, d_xcat);
    cudaGetSymbolAddress((void**)&hA,   d_hA);
    cudaGetSymbolAddress((void**)&cA,   d_cA);
    cudaGetSymbolAddress((void**)&Pa,   d_Pa);
    cudaGetSymbolAddress((void**)&Pf,   d_Pf);
    cudaGetSymbolAddress((void**)&Pb,   d_Pb);
    cudaGetSymbolAddress((void**)&Z,    d_Z);
    cudaGetSymbolAddress((void**)&fwd,  d_fwd);
    cudaGetSymbolAddress((void**)&bwdp, d_bwdp);
    cudaGetSymbolAddress((void**)&cF,   d_cF);
    cudaGetSymbolAddress((void**)&cB,   d_cB);
    cudaGetSymbolAddress((void**)&wbuf, d_w);
    cudaGetSymbolAddress((void**)&wr,   d_wr);

    // rounded weight arena offsets
    float* rWl1 = wr;                 float* rWr1 = rWl1 + 16384;
    float* rWl2 = rWr1 + 16384;       float* rWr2 = rWl2 + 16384;
    float* rWl3 = rWr2 + 16384;       float* rWr3 = rWl3 + 16384;
    float* rWih_a = rWr3 + 16384;     float* rWhh_a = rWih_a + 65536;
    float* rWih_f = rWhh_a + 65536;   float* rWhh_f = rWih_f + 98304;
    float* rWih_b = rWhh_f + 147456;  float* rWhh_b = rWih_b + 98304;

    float* h1 = xcat;
    float* h2 = xcat + NN * CC;
    float* h3 = xcat + 2 * NN * CC;
    float* out = (float*)d_out;

    cudaFuncSetAttribute(tf32_gemm_kernel,
                         cudaFuncAttributeMaxDynamicSharedMemorySize, SMEM_BYTES);

    const int NC_BLK4 = cdiv(NN * CC / 4, 256);
    const int NJ_BLK4 = cdiv(NN * JKH / 4, 256);
    const int NC_BLK  = cdiv(NN * CC, 256);
    dim3 g128(cdiv(NN, BM), 1);
    dim3 g512(cdiv(NN, BM), 4);
    dim3 g768(cdiv(NN, BM), 6);
    dim3 g768x3(cdiv(3 * NN, BM), 6);

    // ---- prep: edge index + tf32 pre-rounding
    detect_idx_kernel<<<1, 32>>>(ei);
    convert_src_kernel<<<cdiv(EE, 256), 256>>>(ei);
    round_kernel<<<cdiv(NN * CC / 4, 256), 256>>>(x, xr, NN * CC / 4);
    round_kernel<<<16, 256>>>(Wl1, rWl1, 4096);
    round_kernel<<<16, 256>>>(Wr1, rWr1, 4096);
    round_kernel<<<16, 256>>>(Wl2, rWl2, 4096);
    round_kernel<<<16, 256>>>(Wr2, rWr2, 4096);
    round_kernel<<<16, 256>>>(Wl3, rWl3, 4096);
    round_kernel<<<16, 256>>>(Wr3, rWr3, 4096);
    round_kernel<<<64, 256>>>(Wih_a, rWih_a, 16384);
    round_kernel<<<64, 256>>>(Whh_a, rWhh_a, 16384);
    round_kernel<<<96, 256>>>(Wih_f, rWih_f, 24576);
    round_kernel<<<144, 256>>>(Whh_f, rWhh_f, 36864);
    round_kernel<<<96, 256>>>(Wih_b, rWih_b, 24576);
    round_kernel<<<144, 256>>>(Whh_b, rWhh_b, 36864);

    // ---- layer 1: mean SAGE + relu (round output)
    agg_mean_kernel<<<NC_BLK, 256>>>(xr, agg);
    tf32_gemm_kernel<<<g128, 256, SMEM_BYTES>>>(agg, xr, rWl1, rWr1, bl1, h1,
                                                NN, 128, 128, 128, 3);

    // ---- layer 2: max SAGE + relu
    agg_max_kernel<<<NC_BLK, 256>>>(h1, agg);
    tf32_gemm_kernel<<<g128, 256, SMEM_BYTES>>>(agg, h1, rWl2, rWr2, bl2, h2,
                                                NN, 128, 128, 128, 3);

    // ---- layer 3: LSTM aggregation (hoisted input projection)
    tf32_gemm_kernel<<<g512, 256, SMEM_BYTES>>>(h2, nullptr, rWih_a, nullptr, nullptr, Pa,
                                                NN, 512, 128, 0, 0);
    for (int t = 0; t < KK; ++t) {
        const float* zr = nullptr;
        if (t > 0) {
            tf32_gemm_kernel<<<g512, 256, SMEM_BYTES>>>(hA, nullptr, rWhh_a, nullptr, nullptr, Z,
                                                        NN, 512, 128, 0, 0);
            zr = Z;
        }
        lstm_gates_kernel<<<NC_BLK4, 256>>>(zr, Pa, srcp, t, bih_a, bhh_a,
                                            hA, cA, 128, t == 0);
    }
    tf32_gemm_kernel<<<g128, 256, SMEM_BYTES>>>(hA, h2, rWl3, rWr3, bl3, h3,
                                                NN, 128, 128, 128, 2);

    // ---- JK bi-LSTM: batched input projections
    tf32_gemm_kernel<<<g768x3, 256, SMEM_BYTES>>>(xcat, nullptr, rWih_f, nullptr, nullptr, Pf,
                                                  3 * NN, 768, 128, 0, 0);
    tf32_gemm_kernel<<<g768x3, 256, SMEM_BYTES>>>(xcat, nullptr, rWih_b, nullptr, nullptr, Pb,
                                                  3 * NN, 768, 128, 0, 0);

    for (int t = 0; t < 3; ++t) {
        const float* zrF = nullptr;
        if (t > 0) {
            tf32_gemm_kernel<<<g768, 256, SMEM_BYTES>>>(fwd + (size_t)(t - 1) * NN * JKH, nullptr,
                                                        rWhh_f, nullptr, nullptr, Z,
                                                        NN, 768, JKH, 0, 0);
            zrF = Z;
        }
        lstm_gates_kernel<<<NJ_BLK4, 256>>>(zrF, Pf + (size_t)t * NN * 768, nullptr, 0,
                                            bih_f, bhh_f,
                                            fwd + (size_t)t * NN * JKH, cF, JKH, t == 0);
        const float* zrB = nullptr;
        if (t > 0) {
            tf32_gemm_kernel<<<g768, 256, SMEM_BYTES>>>(bwdp + (size_t)(3 - t) * NN * JKH, nullptr,
                                                        rWhh_b, nullptr, nullptr, Z,
                                                        NN, 768, JKH, 0, 0);
            zrB = Z;
        }
        lstm_gates_kernel<<<NJ_BLK4, 256>>>(zrB, Pb + (size_t)(2 - t) * NN * 768, nullptr, 0,
                                            bih_b, bhh_b,
                                            bwdp + (size_t)(2 - t) * NN * JKH, cB, JKH, t == 0);
    }

    // ---- attention + combine
    jk_score_kernel<<<cdiv(NN * 32, 256), 256>>>(att_w, att_b, wbuf);
    jk_combine_kernel<<<NC_BLK, 256>>>(out);

    (void)out_size;
}